// round 12
// baseline (speedup 1.0000x reference)
#include <cuda_runtime.h>
#include <cuda_bf16.h>

// Zero-initialized at module load; last block resets them at the end of every
// launch, so every run (correctness + each graph replay) starts from zero.
__device__ float    g_sum;
__device__ unsigned g_arrived;
__device__ unsigned g_done;
__device__ unsigned g_tile;     // dynamic work-stealing tile counter

#define OCC      3
#define NBLOCKS  (148 * OCC)           // all resident (launch_bounds guarantees occ)
#define NTHREADS 512
#define UNROLL   4
#define TILE     (NTHREADS * UNROLL)   // 2048 float4 = 32 KB per tile
#define SMEM_BYTES (2 * TILE * (int)sizeof(float4))   // 64 KB double buffer

// Speculated outcome: S > 0  =>  factor = 4^32 = 2^64 (exact exponent shift).
#define F_GUESS  0x1p64f

__device__ __forceinline__ void cp_async16(float4* smem_dst, const float4* gmem_src) {
    unsigned saddr = (unsigned)__cvta_generic_to_shared(smem_dst);
    asm volatile("cp.async.cg.shared.global [%0], [%1], 16;"
                 :: "r"(saddr), "l"(gmem_src));
}

__global__ void __launch_bounds__(NTHREADS, OCC)
fused_kernel(const float4* __restrict__ in, float4* __restrict__ out, long long n4) {
    extern __shared__ float4 sbuf[];       // [2][TILE]
    long long ftiles = n4 / TILE;          // 4096 full tiles for this shape
    long long rem0   = ftiles * TILE;      // element tail start (== n4 here)

    __shared__ float    sm[NTHREADS / 32];
    __shared__ float    s_factor;
    __shared__ unsigned s_tile[2];         // double-buffered next-tile index

    float s = 0.0f;

    // ---- initial steal + prefetch into buffer 0 ----
    if (threadIdx.x == 0) s_tile[0] = atomicAdd(&g_tile, 1u);
    __syncthreads();
    unsigned t = s_tile[0];
    if ((long long)t < ftiles) {
        long long base = (long long)t * TILE + threadIdx.x;
        #pragma unroll
        for (int u = 0; u < UNROLL; ++u)
            cp_async16(&sbuf[threadIdx.x + u * NTHREADS],
                       &in[base + (long long)u * NTHREADS]);
    }
    asm volatile("cp.async.commit_group;");

    // ---- main loop: prefetch tile k+1 into buf^1 while consuming buf.
    // Each thread reads only the smem region it copied itself, so the only
    // ordering needed is its own cp.async.wait_group. ----
    int b = 0;
    while ((long long)t < ftiles) {
        if (threadIdx.x == 0) s_tile[b ^ 1] = atomicAdd(&g_tile, 1u);
        __syncthreads();
        unsigned tn = s_tile[b ^ 1];

        if ((long long)tn < ftiles) {
            long long basen = (long long)tn * TILE + threadIdx.x;
            #pragma unroll
            for (int u = 0; u < UNROLL; ++u)
                cp_async16(&sbuf[(b ^ 1) * TILE + threadIdx.x + u * NTHREADS],
                           &in[basen + (long long)u * NTHREADS]);
        }
        asm volatile("cp.async.commit_group;");
        asm volatile("cp.async.wait_group 1;");   // current buffer resident

        long long base = (long long)t * TILE + threadIdx.x;
        #pragma unroll
        for (int u = 0; u < UNROLL; ++u) {
            float4 v = sbuf[b * TILE + threadIdx.x + u * NTHREADS];
            s += (v.x + v.y) + (v.z + v.w);
            float4 w;
            w.x = v.x * F_GUESS; w.y = v.y * F_GUESS;
            w.z = v.z * F_GUESS; w.w = v.w * F_GUESS;
            out[base + (long long)u * NTHREADS] = w;
        }

        b ^= 1;
        t = tn;
    }
    asm volatile("cp.async.wait_group 0;");

    // element remainder (empty for this shape; kept for generality)
    for (long long j = rem0 + (long long)blockIdx.x * NTHREADS + threadIdx.x;
         j < n4; j += (long long)gridDim.x * NTHREADS) {
        float4 v = in[j];
        s += (v.x + v.y) + (v.z + v.w);
        float4 w;
        w.x = v.x * F_GUESS; w.y = v.y * F_GUESS;
        w.z = v.z * F_GUESS; w.w = v.w * F_GUESS;
        out[j] = w;
    }

    #pragma unroll
    for (int o = 16; o > 0; o >>= 1)
        s += __shfl_xor_sync(0xffffffffu, s, o);

    int lane = threadIdx.x & 31;
    int warp = threadIdx.x >> 5;
    if (lane == 0) sm[warp] = s;
    __syncthreads();
    if (warp == 0) {
        s = (lane < (NTHREADS >> 5)) ? sm[lane] : 0.0f;
        #pragma unroll
        for (int o = 16; o > 0; o >>= 1)
            s += __shfl_xor_sync(0xffffffffu, s, o);
        if (lane == 0) {
            atomicAdd(&g_sum, s);
            __threadfence();
            atomicAdd(&g_arrived, 1u);
        }
    }

    // ---- grid barrier: wait for all blocks' partials (all resident) ----
    if (threadIdx.x == 0) {
        volatile unsigned* pa = &g_arrived;
        while (*pa < gridDim.x) { }
        __threadfence();
        volatile float* ps = &g_sum;
        float S = *ps;
        // S>0: 4^32 = 2^64.  S<0: -2*4^31 = -2^63.  S==0: (-2)^32 = 2^32.
        s_factor = (S > 0.0f) ? 0x1p64f : ((S < 0.0f) ? -0x1p63f : 0x1p32f);
    }
    __syncthreads();
    float f = s_factor;

    // ---- phase 2 (mispredict repair only): rewrite with correct factor. ----
    if (f != F_GUESS) {
        for (long long k = (long long)blockIdx.x * NTHREADS + threadIdx.x;
             k < n4; k += (long long)gridDim.x * NTHREADS) {
            float4 v = in[k];
            v.x *= f; v.y *= f; v.z *= f; v.w *= f;
            out[k] = v;
        }
    }

    // ---- epilogue: last block resets globals for the next replay ----
    __syncthreads();
    if (threadIdx.x == 0) {
        __threadfence();
        unsigned d = atomicAdd(&g_done, 1u);
        if (d == gridDim.x - 1) {
            g_sum     = 0.0f;
            g_arrived = 0u;
            g_done    = 0u;
            g_tile    = 0u;
            __threadfence();
        }
    }
}

extern "C" void kernel_launch(void* const* d_in, const int* in_sizes, int n_in,
                              void* d_out, int out_size) {
    const float4* in  = (const float4*)d_in[0];
    float4*       out = (float4*)d_out;
    long long n  = (long long)in_sizes[0];   // 32*1024*1024
    long long n4 = n >> 2;                   // float4 count (n divisible by 4)

    // Opt in to 64 KB dynamic smem (idempotent; not a stream op, capture-safe).
    cudaFuncSetAttribute(fused_kernel,
                         cudaFuncAttributeMaxDynamicSharedMemorySize, SMEM_BYTES);

    fused_kernel<<<NBLOCKS, NTHREADS, SMEM_BYTES>>>(in, out, n4);
}

// round 13
// speedup vs baseline: 1.0507x; 1.0507x over previous
#include <cuda_runtime.h>
#include <cuda_bf16.h>

// Zero-initialized at module load; last block resets them at the end of every
// launch, so every run (correctness + each graph replay) starts from zero.
__device__ float    g_sum;
__device__ unsigned g_arrived;
__device__ unsigned g_ready;    // 0 = pending; else factor code (1,2,3)
__device__ unsigned g_done;
__device__ unsigned g_tile;     // dynamic work-stealing tile counter

#define OCC      3
#define NBLOCKS  (148 * OCC)           // all resident (launch_bounds guarantees occ)
#define NTHREADS 512
#define UNROLL   4
#define TILE     (NTHREADS * UNROLL)   // 2048 float4 = 32 KB per tile

// Speculated outcome: S > 0  =>  factor = 4^32 = 2^64 (exact exponent shift).
#define F_GUESS  0x1p64f

__global__ void __launch_bounds__(NTHREADS, OCC)
fused_kernel(const float4* __restrict__ in, float4* __restrict__ out, long long n4) {
    long long ftiles = n4 / TILE;          // 4096 full tiles for this shape
    long long rem0   = ftiles * TILE;      // element tail start (== n4 here)

    __shared__ float    sm[NTHREADS / 32];
    __shared__ float    s_factor;
    __shared__ unsigned s_tile[2];         // double-buffered next-tile index

    // ---- phase 1: dynamic tiles; next tile index fetched while current
    // tile's loads are in flight (ATOMG hidden under memory-bound body). ----
    float s = 0.0f;
    if (threadIdx.x == 0) s_tile[0] = atomicAdd(&g_tile, 1u);
    __syncthreads();
    unsigned t   = s_tile[0];
    int      buf = 0;
    while ((long long)t < ftiles) {
        if (threadIdx.x == 0) s_tile[buf ^ 1] = atomicAdd(&g_tile, 1u);

        long long base = (long long)t * TILE + threadIdx.x;
        float4 v[UNROLL];
        #pragma unroll
        for (int u = 0; u < UNROLL; ++u)
            v[u] = in[base + (long long)u * NTHREADS];
        #pragma unroll
        for (int u = 0; u < UNROLL; ++u) {
            s += (v[u].x + v[u].y) + (v[u].z + v[u].w);
            float4 w;
            w.x = v[u].x * F_GUESS; w.y = v[u].y * F_GUESS;
            w.z = v[u].z * F_GUESS; w.w = v[u].w * F_GUESS;
            out[base + (long long)u * NTHREADS] = w;
        }

        __syncthreads();
        buf ^= 1;
        t = s_tile[buf];
    }
    // element remainder (empty for this shape; kept for generality)
    for (long long j = rem0 + (long long)blockIdx.x * NTHREADS + threadIdx.x;
         j < n4; j += (long long)gridDim.x * NTHREADS) {
        float4 v = in[j];
        s += (v.x + v.y) + (v.z + v.w);
        float4 w;
        w.x = v.x * F_GUESS; w.y = v.y * F_GUESS;
        w.z = v.z * F_GUESS; w.w = v.w * F_GUESS;
        out[j] = w;
    }

    #pragma unroll
    for (int o = 16; o > 0; o >>= 1)
        s += __shfl_xor_sync(0xffffffffu, s, o);

    int lane = threadIdx.x & 31;
    int warp = threadIdx.x >> 5;
    if (lane == 0) sm[warp] = s;
    __syncthreads();
    if (warp == 0) {
        s = (lane < (NTHREADS >> 5)) ? sm[lane] : 0.0f;
        #pragma unroll
        for (int o = 16; o > 0; o >>= 1)
            s += __shfl_xor_sync(0xffffffffu, s, o);
        if (lane == 0) {
            atomicAdd(&g_sum, s);
            __threadfence();
            // Last arriver computes the factor code and publishes it in ONE
            // word: spinners poll a single location written once (broadcast-
            // friendly), instead of a counter invalidated on every arrival.
            unsigned a = atomicAdd(&g_arrived, 1u);
            if (a == gridDim.x - 1) {
                float S = *(volatile float*)&g_sum;
                unsigned code = (S > 0.0f) ? 1u : ((S < 0.0f) ? 2u : 3u);
                __threadfence();
                atomicExch(&g_ready, code);
            }
        }
    }

    // ---- barrier wait: poll the single ready/factor word ----
    if (threadIdx.x == 0) {
        unsigned code;
        volatile unsigned* pr = &g_ready;
        while ((code = *pr) == 0u) { }
        // S>0: 4^32 = 2^64.  S<0: -2*4^31 = -2^63.  S==0: (-2)^32 = 2^32.
        s_factor = (code == 1u) ? 0x1p64f : ((code == 2u) ? -0x1p63f : 0x1p32f);
    }
    __syncthreads();
    float f = s_factor;

    // ---- phase 2 (mispredict repair only): rewrite with correct factor. ----
    if (f != F_GUESS) {
        for (long long k = (long long)blockIdx.x * NTHREADS + threadIdx.x;
             k < n4; k += (long long)gridDim.x * NTHREADS) {
            float4 v = in[k];
            v.x *= f; v.y *= f; v.z *= f; v.w *= f;
            out[k] = v;
        }
    }

    // ---- epilogue: last block resets globals for the next replay ----
    __syncthreads();
    if (threadIdx.x == 0) {
        __threadfence();
        unsigned d = atomicAdd(&g_done, 1u);
        if (d == gridDim.x - 1) {
            g_sum     = 0.0f;
            g_arrived = 0u;
            g_ready   = 0u;
            g_done    = 0u;
            g_tile    = 0u;
            __threadfence();
        }
    }
}

extern "C" void kernel_launch(void* const* d_in, const int* in_sizes, int n_in,
                              void* d_out, int out_size) {
    const float4* in  = (const float4*)d_in[0];
    float4*       out = (float4*)d_out;
    long long n  = (long long)in_sizes[0];   // 32*1024*1024
    long long n4 = n >> 2;                   // float4 count (n divisible by 4)

    fused_kernel<<<NBLOCKS, NTHREADS>>>(in, out, n4);
}

// round 14
// speedup vs baseline: 1.0802x; 1.0281x over previous
#include <cuda_runtime.h>
#include <cuda_bf16.h>

// Zero-initialized at module load; last block resets them at the end of every
// launch, so every run (correctness + each graph replay) starts from zero.
__device__ float    g_sum;
__device__ unsigned g_arrived;
__device__ unsigned g_ready;    // 0 = pending; else factor code (1,2,3)
__device__ unsigned g_done;
__device__ unsigned g_tile;     // steal counter for tiles >= NBLOCKS

#define NBLOCKS  148
#define NTHREADS 1024
#define UNROLL   4
#define TILE     (NTHREADS * UNROLL)   // 4096 float4 = 64 KB per tile

// Speculated outcome: S > 0  =>  factor = 4^32 = 2^64 (exact exponent shift).
#define F_GUESS  0x1p64f

__global__ void __launch_bounds__(NTHREADS, 1)
fused_kernel(const float4* __restrict__ in, float4* __restrict__ out, long long n4) {
    long long ftiles = n4 / TILE;          // 2048 full tiles for this shape
    long long rem0   = ftiles * TILE;      // element tail start (== n4 here)

    __shared__ float    sm[NTHREADS / 32];
    __shared__ float    s_factor;
    __shared__ unsigned s_tile[2];         // double-buffered next-tile index

    // ---- phase 1: first tile is static (blockIdx) so loads start at cycle 0;
    // subsequent tiles stolen dynamically, counter mapping c -> NBLOCKS + c.
    // Next index is fetched while current tile's loads are in flight. ----
    float s = 0.0f;
    unsigned t   = blockIdx.x;
    int      buf = 0;
    while ((long long)t < ftiles) {
        if (threadIdx.x == 0)
            s_tile[buf] = NBLOCKS + atomicAdd(&g_tile, 1u);

        long long base = (long long)t * TILE + threadIdx.x;
        float4 v[UNROLL];
        #pragma unroll
        for (int u = 0; u < UNROLL; ++u)
            v[u] = in[base + (long long)u * NTHREADS];
        #pragma unroll
        for (int u = 0; u < UNROLL; ++u) {
            s += (v[u].x + v[u].y) + (v[u].z + v[u].w);
            float4 w;
            w.x = v[u].x * F_GUESS; w.y = v[u].y * F_GUESS;
            w.z = v[u].z * F_GUESS; w.w = v[u].w * F_GUESS;
            out[base + (long long)u * NTHREADS] = w;
        }

        __syncthreads();
        t   = s_tile[buf];
        buf ^= 1;
    }
    // element remainder (empty for this shape; kept for generality)
    for (long long j = rem0 + (long long)blockIdx.x * NTHREADS + threadIdx.x;
         j < n4; j += (long long)gridDim.x * NTHREADS) {
        float4 v = in[j];
        s += (v.x + v.y) + (v.z + v.w);
        float4 w;
        w.x = v.x * F_GUESS; w.y = v.y * F_GUESS;
        w.z = v.z * F_GUESS; w.w = v.w * F_GUESS;
        out[j] = w;
    }

    #pragma unroll
    for (int o = 16; o > 0; o >>= 1)
        s += __shfl_xor_sync(0xffffffffu, s, o);

    int lane = threadIdx.x & 31;
    int warp = threadIdx.x >> 5;
    if (lane == 0) sm[warp] = s;
    __syncthreads();
    if (warp == 0) {
        s = (lane < (NTHREADS >> 5)) ? sm[lane] : 0.0f;
        #pragma unroll
        for (int o = 16; o > 0; o >>= 1)
            s += __shfl_xor_sync(0xffffffffu, s, o);
        if (lane == 0) {
            atomicAdd(&g_sum, s);
            __threadfence();
            // Last arriver computes factor code, publishes it in ONE word:
            // spinners poll a single location written once.
            unsigned a = atomicAdd(&g_arrived, 1u);
            if (a == gridDim.x - 1) {
                float S = *(volatile float*)&g_sum;
                unsigned code = (S > 0.0f) ? 1u : ((S < 0.0f) ? 2u : 3u);
                __threadfence();
                atomicExch(&g_ready, code);
            }
        }
    }

    // ---- barrier wait: poll the single ready/factor word ----
    if (threadIdx.x == 0) {
        unsigned code;
        volatile unsigned* pr = &g_ready;
        while ((code = *pr) == 0u) { }
        // S>0: 4^32 = 2^64.  S<0: -2*4^31 = -2^63.  S==0: (-2)^32 = 2^32.
        s_factor = (code == 1u) ? 0x1p64f : ((code == 2u) ? -0x1p63f : 0x1p32f);
    }
    __syncthreads();
    float f = s_factor;

    // ---- phase 2 (mispredict repair only): rewrite with correct factor. ----
    if (f != F_GUESS) {
        for (long long k = (long long)blockIdx.x * NTHREADS + threadIdx.x;
             k < n4; k += (long long)gridDim.x * NTHREADS) {
            float4 v = in[k];
            v.x *= f; v.y *= f; v.z *= f; v.w *= f;
            out[k] = v;
        }
    }

    // ---- epilogue: last block resets globals for the next replay ----
    __syncthreads();
    if (threadIdx.x == 0) {
        __threadfence();
        unsigned d = atomicAdd(&g_done, 1u);
        if (d == gridDim.x - 1) {
            g_sum     = 0.0f;
            g_arrived = 0u;
            g_ready   = 0u;
            g_done    = 0u;
            g_tile    = 0u;
            __threadfence();
        }
    }
}

extern "C" void kernel_launch(void* const* d_in, const int* in_sizes, int n_in,
                              void* d_out, int out_size) {
    const float4* in  = (const float4*)d_in[0];
    float4*       out = (float4*)d_out;
    long long n  = (long long)in_sizes[0];   // 32*1024*1024
    long long n4 = n >> 2;                   // float4 count (n divisible by 4)

    fused_kernel<<<NBLOCKS, NTHREADS>>>(in, out, n4);
}

// round 15
// speedup vs baseline: 1.1099x; 1.0275x over previous
#include <cuda_runtime.h>
#include <cuda_bf16.h>

// Zero-initialized at module load; the LAST-arriving block resets them at the
// end of every launch, so every run (correctness + each graph replay) starts
// from zero.
__device__ float    g_sum;
__device__ unsigned g_arrived;
__device__ unsigned g_tile;     // steal counter for tiles >= NBLOCKS

#define NBLOCKS  148
#define NTHREADS 1024
#define UNROLL   4
#define TILE     (NTHREADS * UNROLL)   // 4096 float4 = 64 KB per tile

// Speculated outcome: S > 0  =>  factor = 4^32 = 2^64 (exact exponent shift).
#define F_GUESS  0x1p64f

__global__ void __launch_bounds__(NTHREADS, 1)
fused_kernel(const float4* __restrict__ in, float4* __restrict__ out, long long n4) {
    long long ftiles = n4 / TILE;          // 2048 full tiles for this shape
    long long rem0   = ftiles * TILE;      // element tail start (== n4 here)

    __shared__ float    sm[NTHREADS / 32];
    __shared__ unsigned s_tile[2];         // double-buffered next-tile index
    __shared__ unsigned s_repair;          // 0 = exit; else factor code

    // ---- phase 1: first tile static (loads start at cycle 0); rest stolen
    // dynamically (counter c -> tile NBLOCKS + c), next index fetched while
    // the current tile's loads are in flight. Speculatively writes
    // out = in * F_GUESS alongside the sum. ----
    float s = 0.0f;
    unsigned t   = blockIdx.x;
    int      buf = 0;
    while ((long long)t < ftiles) {
        if (threadIdx.x == 0)
            s_tile[buf] = NBLOCKS + atomicAdd(&g_tile, 1u);

        long long base = (long long)t * TILE + threadIdx.x;
        float4 v[UNROLL];
        #pragma unroll
        for (int u = 0; u < UNROLL; ++u)
            v[u] = in[base + (long long)u * NTHREADS];
        #pragma unroll
        for (int u = 0; u < UNROLL; ++u) {
            s += (v[u].x + v[u].y) + (v[u].z + v[u].w);
            float4 w;
            w.x = v[u].x * F_GUESS; w.y = v[u].y * F_GUESS;
            w.z = v[u].z * F_GUESS; w.w = v[u].w * F_GUESS;
            out[base + (long long)u * NTHREADS] = w;
        }

        __syncthreads();
        t   = s_tile[buf];
        buf ^= 1;
    }
    // element remainder (empty for this shape; kept for generality)
    for (long long j = rem0 + (long long)blockIdx.x * NTHREADS + threadIdx.x;
         j < n4; j += (long long)gridDim.x * NTHREADS) {
        float4 v = in[j];
        s += (v.x + v.y) + (v.z + v.w);
        float4 w;
        w.x = v.x * F_GUESS; w.y = v.y * F_GUESS;
        w.z = v.z * F_GUESS; w.w = v.w * F_GUESS;
        out[j] = w;
    }

    // ---- block reduce ----
    #pragma unroll
    for (int o = 16; o > 0; o >>= 1)
        s += __shfl_xor_sync(0xffffffffu, s, o);

    int lane = threadIdx.x & 31;
    int warp = threadIdx.x >> 5;
    if (lane == 0) sm[warp] = s;
    __syncthreads();
    if (warp == 0) {
        s = (lane < (NTHREADS >> 5)) ? sm[lane] : 0.0f;
        #pragma unroll
        for (int o = 16; o > 0; o >>= 1)
            s += __shfl_xor_sync(0xffffffffu, s, o);
    }

    // ---- barrier-free finish: publish partial, arrive, and EXIT.
    // The fence orders this block's speculative out-stores before its arrival,
    // so when the last arriver sees all arrivals, every store is visible.
    // Only the LAST arriver checks the sign; on mispredict its block alone
    // repairs the whole output (slow path, never taken when the guess holds).
    if (threadIdx.x == 0) {
        atomicAdd(&g_sum, s);
        __threadfence();
        unsigned a = atomicAdd(&g_arrived, 1u);
        unsigned code = 0u;
        if (a == gridDim.x - 1) {
            float S = *(volatile float*)&g_sum;
            // S>0: 4^32 = 2^64.  S<0: -2*4^31 = -2^63.  S==0: (-2)^32 = 2^32.
            float f = (S > 0.0f) ? 0x1p64f : ((S < 0.0f) ? -0x1p63f : 0x1p32f);
            if (f != F_GUESS)
                code = (S < 0.0f) ? 2u : 3u;
            // reset globals for the next replay (no other block is running)
            g_sum     = 0.0f;
            g_arrived = 0u;
            g_tile    = 0u;
            __threadfence();
        }
        s_repair = code;
    }
    __syncthreads();

    // ---- mispredict repair (cold path): this single block rewrites all. ----
    unsigned code = s_repair;
    if (code != 0u) {
        float f = (code == 2u) ? -0x1p63f : 0x1p32f;
        for (long long k = threadIdx.x; k < n4; k += NTHREADS) {
            float4 v = in[k];
            v.x *= f; v.y *= f; v.z *= f; v.w *= f;
            out[k] = v;
        }
    }
}

extern "C" void kernel_launch(void* const* d_in, const int* in_sizes, int n_in,
                              void* d_out, int out_size) {
    const float4* in  = (const float4*)d_in[0];
    float4*       out = (float4*)d_out;
    long long n  = (long long)in_sizes[0];   // 32*1024*1024
    long long n4 = n >> 2;                   // float4 count (n divisible by 4)

    fused_kernel<<<NBLOCKS, NTHREADS>>>(in, out, n4);
}

// round 16
// speedup vs baseline: 1.1348x; 1.0225x over previous
#include <cuda_runtime.h>
#include <cuda_bf16.h>

// Zero-initialized at module load; the LAST-arriving block resets them at the
// end of every launch, so every run (correctness + each graph replay) starts
// from zero.
__device__ float    g_sum;
__device__ unsigned g_arrived;
__device__ unsigned g_tile;     // steal counter for tiles >= NBLOCKS

#define NBLOCKS  148
#define NTHREADS 1024
#define UNROLL   2                      // in 32-byte (float8) units
#define TILE8    (NTHREADS * UNROLL)    // 2048 float8 = 64 KB per tile

// Speculated outcome: S > 0  =>  factor = 4^32 = 2^64 (exact exponent shift).
#define F_GUESS  0x1p64f

// 256-bit global load (non-coherent) / store — sm_100+.
__device__ __forceinline__ void ldg256(const float* p, float* v) {
    asm volatile("ld.global.nc.v8.f32 {%0,%1,%2,%3,%4,%5,%6,%7}, [%8];"
                 : "=f"(v[0]), "=f"(v[1]), "=f"(v[2]), "=f"(v[3]),
                   "=f"(v[4]), "=f"(v[5]), "=f"(v[6]), "=f"(v[7])
                 : "l"(p));
}
__device__ __forceinline__ void stg256(float* p, const float* v) {
    asm volatile("st.global.v8.f32 [%0], {%1,%2,%3,%4,%5,%6,%7,%8};"
                 :: "l"(p),
                    "f"(v[0]), "f"(v[1]), "f"(v[2]), "f"(v[3]),
                    "f"(v[4]), "f"(v[5]), "f"(v[6]), "f"(v[7])
                 : "memory");
}

__global__ void __launch_bounds__(NTHREADS, 1)
fused_kernel(const float* __restrict__ in, float* __restrict__ out, long long n) {
    long long n8     = n >> 3;             // float8 count
    long long ftiles = n8 / TILE8;         // 2048 full tiles for this shape
    long long rem0   = ftiles * TILE8 * 8; // element tail start (== n here)

    __shared__ float    sm[NTHREADS / 32];
    __shared__ unsigned s_tile[2];         // double-buffered next-tile index
    __shared__ unsigned s_repair;          // 0 = exit; else factor code

    // ---- phase 1: first tile static (loads start at cycle 0); rest stolen
    // dynamically (counter c -> tile NBLOCKS + c), next index fetched while
    // the current tile's loads are in flight. Speculatively writes
    // out = in * F_GUESS alongside the sum. 256-bit ld/st. ----
    float s = 0.0f;
    unsigned t   = blockIdx.x;
    int      buf = 0;
    while ((long long)t < ftiles) {
        if (threadIdx.x == 0)
            s_tile[buf] = NBLOCKS + atomicAdd(&g_tile, 1u);

        long long base = (long long)t * TILE8 + threadIdx.x;   // float8 units
        float v[UNROLL][8];
        #pragma unroll
        for (int u = 0; u < UNROLL; ++u)
            ldg256(in + (base + (long long)u * NTHREADS) * 8, v[u]);
        #pragma unroll
        for (int u = 0; u < UNROLL; ++u) {
            float w[8];
            #pragma unroll
            for (int e = 0; e < 8; ++e) {
                s += v[u][e];
                w[e] = v[u][e] * F_GUESS;
            }
            stg256(out + (base + (long long)u * NTHREADS) * 8, w);
        }

        __syncthreads();
        t   = s_tile[buf];
        buf ^= 1;
    }
    // element remainder in float4 steps (empty for this shape) ----
    for (long long j = (rem0 >> 2) + (long long)blockIdx.x * NTHREADS + threadIdx.x;
         j < (n >> 2); j += (long long)gridDim.x * NTHREADS) {
        float4 v = ((const float4*)in)[j];
        s += (v.x + v.y) + (v.z + v.w);
        float4 w;
        w.x = v.x * F_GUESS; w.y = v.y * F_GUESS;
        w.z = v.z * F_GUESS; w.w = v.w * F_GUESS;
        ((float4*)out)[j] = w;
    }

    // ---- block reduce ----
    #pragma unroll
    for (int o = 16; o > 0; o >>= 1)
        s += __shfl_xor_sync(0xffffffffu, s, o);

    int lane = threadIdx.x & 31;
    int warp = threadIdx.x >> 5;
    if (lane == 0) sm[warp] = s;
    __syncthreads();
    if (warp == 0) {
        s = (lane < (NTHREADS >> 5)) ? sm[lane] : 0.0f;
        #pragma unroll
        for (int o = 16; o > 0; o >>= 1)
            s += __shfl_xor_sync(0xffffffffu, s, o);
    }

    // ---- barrier-free finish: publish partial, arrive, and EXIT.
    // The fence orders this block's speculative out-stores before its arrival,
    // so when the last arriver sees all arrivals, every store is visible.
    // Only the LAST arriver checks the sign; on mispredict its block alone
    // repairs the whole output (cold path, never taken when the guess holds).
    if (threadIdx.x == 0) {
        atomicAdd(&g_sum, s);
        __threadfence();
        unsigned a = atomicAdd(&g_arrived, 1u);
        unsigned code = 0u;
        if (a == gridDim.x - 1) {
            float S = *(volatile float*)&g_sum;
            // S>0: 4^32 = 2^64.  S<0: -2*4^31 = -2^63.  S==0: (-2)^32 = 2^32.
            float f = (S > 0.0f) ? 0x1p64f : ((S < 0.0f) ? -0x1p63f : 0x1p32f);
            if (f != F_GUESS)
                code = (S < 0.0f) ? 2u : 3u;
            // reset globals for the next replay (no other block is running)
            g_sum     = 0.0f;
            g_arrived = 0u;
            g_tile    = 0u;
            __threadfence();
        }
        s_repair = code;
    }
    __syncthreads();

    // ---- mispredict repair (cold path): this single block rewrites all. ----
    unsigned code = s_repair;
    if (code != 0u) {
        float f = (code == 2u) ? -0x1p63f : 0x1p32f;
        for (long long k = threadIdx.x; k < (n >> 2); k += NTHREADS) {
            float4 v = ((const float4*)in)[k];
            v.x *= f; v.y *= f; v.z *= f; v.w *= f;
            ((float4*)out)[k] = v;
        }
    }
}

extern "C" void kernel_launch(void* const* d_in, const int* in_sizes, int n_in,
                              void* d_out, int out_size) {
    const float* in  = (const float*)d_in[0];
    float*       out = (float*)d_out;
    long long n = (long long)in_sizes[0];   // 32*1024*1024

    fused_kernel<<<NBLOCKS, NTHREADS>>>(in, out, n);
}

// round 17
// speedup vs baseline: 1.1356x; 1.0007x over previous
#include <cuda_runtime.h>
#include <cuda_bf16.h>

// Zero-initialized at module load; the LAST-arriving block resets them at the
// end of every launch, so every run (correctness + each graph replay) starts
// from zero.
__device__ float    g_sum;
__device__ unsigned g_arrived;
__device__ unsigned g_tile;     // steal counter for tiles >= NBLOCKS

#define NBLOCKS  148
#define NTHREADS 1024
#define UNROLL8  2                      // 32-byte (float8) slots per thread
#define TILE8    (NTHREADS * UNROLL8)   // 2048 float8 = 64 KB per tile

// Speculated outcome: S > 0  =>  factor = 4^32 = 2^64 (exact exponent shift).
#define F_GUESS  0x1p64f

// 256-bit global store from two float4 values — sm_100+.
__device__ __forceinline__ void stg256(float* p, float4 a, float4 b) {
    asm volatile("st.global.v8.f32 [%0], {%1,%2,%3,%4,%5,%6,%7,%8};"
                 :: "l"(p),
                    "f"(a.x), "f"(a.y), "f"(a.z), "f"(a.w),
                    "f"(b.x), "f"(b.y), "f"(b.z), "f"(b.w)
                 : "memory");
}

__global__ void __launch_bounds__(NTHREADS, 1)
fused_kernel(const float* __restrict__ in, float* __restrict__ out, long long n) {
    long long n8     = n >> 3;             // float8 count
    long long ftiles = n8 / TILE8;         // 2048 full tiles for this shape
    long long rem0   = ftiles * TILE8 * 8; // element tail start (== n here)

    const float4* in4 = (const float4*)in;

    __shared__ float    sm[NTHREADS / 32];
    __shared__ unsigned s_tile[2];         // double-buffered next-tile index
    __shared__ unsigned s_repair;          // 0 = exit; else factor code

    // ---- phase 1: first tile static (loads start at cycle 0); rest stolen
    // dynamically (counter c -> tile NBLOCKS + c), next index fetched while
    // the current tile's loads are in flight. Loads: 4x LDG.128 (MLP=4).
    // Stores: 2x STG.256 (half the store issue cost). Speculatively writes
    // out = in * F_GUESS alongside the sum. ----
    float s = 0.0f;
    unsigned t   = blockIdx.x;
    int      buf = 0;
    while ((long long)t < ftiles) {
        if (threadIdx.x == 0)
            s_tile[buf] = NBLOCKS + atomicAdd(&g_tile, 1u);

        long long s0 = (long long)t * TILE8 + threadIdx.x;   // float8 slot 0
        long long s1 = s0 + NTHREADS;                        // float8 slot 1

        // 4 independent 128-bit loads in flight
        float4 a0 = in4[2 * s0];
        float4 a1 = in4[2 * s0 + 1];
        float4 b0 = in4[2 * s1];
        float4 b1 = in4[2 * s1 + 1];

        s += (a0.x + a0.y) + (a0.z + a0.w);
        s += (a1.x + a1.y) + (a1.z + a1.w);
        s += (b0.x + b0.y) + (b0.z + b0.w);
        s += (b1.x + b1.y) + (b1.z + b1.w);

        float4 wa0, wa1, wb0, wb1;
        wa0.x = a0.x * F_GUESS; wa0.y = a0.y * F_GUESS;
        wa0.z = a0.z * F_GUESS; wa0.w = a0.w * F_GUESS;
        wa1.x = a1.x * F_GUESS; wa1.y = a1.y * F_GUESS;
        wa1.z = a1.z * F_GUESS; wa1.w = a1.w * F_GUESS;
        wb0.x = b0.x * F_GUESS; wb0.y = b0.y * F_GUESS;
        wb0.z = b0.z * F_GUESS; wb0.w = b0.w * F_GUESS;
        wb1.x = b1.x * F_GUESS; wb1.y = b1.y * F_GUESS;
        wb1.z = b1.z * F_GUESS; wb1.w = b1.w * F_GUESS;

        stg256(out + s0 * 8, wa0, wa1);
        stg256(out + s1 * 8, wb0, wb1);

        __syncthreads();
        t   = s_tile[buf];
        buf ^= 1;
    }
    // element remainder in float4 steps (empty for this shape) ----
    for (long long j = (rem0 >> 2) + (long long)blockIdx.x * NTHREADS + threadIdx.x;
         j < (n >> 2); j += (long long)gridDim.x * NTHREADS) {
        float4 v = in4[j];
        s += (v.x + v.y) + (v.z + v.w);
        float4 w;
        w.x = v.x * F_GUESS; w.y = v.y * F_GUESS;
        w.z = v.z * F_GUESS; w.w = v.w * F_GUESS;
        ((float4*)out)[j] = w;
    }

    // ---- block reduce ----
    #pragma unroll
    for (int o = 16; o > 0; o >>= 1)
        s += __shfl_xor_sync(0xffffffffu, s, o);

    int lane = threadIdx.x & 31;
    int warp = threadIdx.x >> 5;
    if (lane == 0) sm[warp] = s;
    __syncthreads();
    if (warp == 0) {
        s = (lane < (NTHREADS >> 5)) ? sm[lane] : 0.0f;
        #pragma unroll
        for (int o = 16; o > 0; o >>= 1)
            s += __shfl_xor_sync(0xffffffffu, s, o);
    }

    // ---- barrier-free finish: publish partial, arrive, and EXIT.
    // The fence orders this block's speculative out-stores before its arrival,
    // so when the last arriver sees all arrivals, every store is visible.
    // Only the LAST arriver checks the sign; on mispredict its block alone
    // repairs the whole output (cold path, never taken when the guess holds).
    if (threadIdx.x == 0) {
        atomicAdd(&g_sum, s);
        __threadfence();
        unsigned a = atomicAdd(&g_arrived, 1u);
        unsigned code = 0u;
        if (a == gridDim.x - 1) {
            float S = *(volatile float*)&g_sum;
            // S>0: 4^32 = 2^64.  S<0: -2*4^31 = -2^63.  S==0: (-2)^32 = 2^32.
            float f = (S > 0.0f) ? 0x1p64f : ((S < 0.0f) ? -0x1p63f : 0x1p32f);
            if (f != F_GUESS)
                code = (S < 0.0f) ? 2u : 3u;
            // reset globals for the next replay (no other block is running)
            g_sum     = 0.0f;
            g_arrived = 0u;
            g_tile    = 0u;
            __threadfence();
        }
        s_repair = code;
    }
    __syncthreads();

    // ---- mispredict repair (cold path): this single block rewrites all. ----
    unsigned code = s_repair;
    if (code != 0u) {
        float f = (code == 2u) ? -0x1p63f : 0x1p32f;
        for (long long k = threadIdx.x; k < (n >> 2); k += NTHREADS) {
            float4 v = in4[k];
            v.x *= f; v.y *= f; v.z *= f; v.w *= f;
            ((float4*)out)[k] = v;
        }
    }
}

extern "C" void kernel_launch(void* const* d_in, const int* in_sizes, int n_in,
                              void* d_out, int out_size) {
    const float* in  = (const float*)d_in[0];
    float*       out = (float*)d_out;
    long long n = (long long)in_sizes[0];   // 32*1024*1024

    fused_kernel<<<NBLOCKS, NTHREADS>>>(in, out, n);
}